// round 8
// baseline (speedup 1.0000x reference)
#include <cuda_runtime.h>

#define WIDTH   512
#define HEIGHT  512
#define TH      8                  // output rows per CTA
#define NTH     512                // threads per CTA (1 per column)
#define ROWB    (WIDTH * 16)       // bytes per SMEM vb row (512 x 16B tuples)
#define SMEM_BYTES (TH * ROWB)     // 65536

typedef unsigned long long u64;

// reflect padding (pad=3 < dim, single reflection suffices)
__device__ __forceinline__ int refl(int i, int n) {
    i = i < 0 ? -i : i;
    return i >= n ? 2 * n - 2 - i : i;
}

// XOR swizzle: byte offset of tuple #x within a vb row.
// x' = x ^ ((x>>3)&7): stride-8 accesses (stage-2 lanes) land on distinct
// 16B slots -> conflict-free LDS.128 / STS.128.
__device__ __forceinline__ unsigned vboff(int x) {
    return (unsigned)((x ^ ((x >> 3) & 7)) << 4);
}

__device__ __forceinline__ u64 pack2(float lo, float hi) {
    u64 r; asm("mov.b64 %0, {%1, %2};" : "=l"(r) : "f"(lo), "f"(hi)); return r;
}
__device__ __forceinline__ void unpack2(u64 v, float& lo, float& hi) {
    asm("mov.b64 {%0, %1}, %2;" : "=f"(lo), "=f"(hi) : "l"(v));
}
// packed dual FMA -> FFMA2 in SASS (PTX-only form)
__device__ __forceinline__ u64 fma2(u64 a, u64 b, u64 c) {
    u64 d; asm("fma.rn.f32x2 %0, %1, %2, %3;" : "=l"(d) : "l"(a), "l"(b), "l"(c));
    return d;
}
__device__ __forceinline__ float frsq_ap(float x) {
    float r; asm("rsqrt.approx.f32 %0, %1;" : "=f"(r) : "f"(x)); return r;
}

__global__ __launch_bounds__(NTH, 2)
void adain_local_kernel(const float* __restrict__ content,
                        const float* __restrict__ style,
                        float* __restrict__ out) {
    extern __shared__ unsigned char sm[];

    // Gaussian taps (sigma=1, k=7), normalized; packed into both f32x2 lanes.
    const float G[7] = {0.0044330481752437f, 0.0540055826224143f,
                        0.2420362293761143f, 0.3990502746173879f,
                        0.2420362293761143f, 0.0540055826224143f,
                        0.0044330481752437f};
    u64 G2[7];
    #pragma unroll
    for (int k = 0; k < 7; ++k) G2[k] = pack2(G[k], G[k]);

    const int plane = blockIdx.y;
    const int y0    = blockIdx.x * TH;
    const size_t pb = (size_t)plane * (WIDTH * HEIGHT);
    const float* cp = content + pb;
    const float* sp = style   + pb;
    float*       op = out     + pb;
    const int tid = threadIdx.x;

    // -------- Stage 1: vertical 7-tap blur; 1 thread per column -------------
    {
        const int x = tid;                     // 0..511, coalesced per row
        u64 rc[7], rs[7];                      // ring: packed (v, v^2)
        #pragma unroll
        for (int i = 0; i < TH + 6; ++i) {
            const int gy = refl(y0 - 3 + i, HEIGHT);
            const float c = __ldg(cp + gy * WIDTH + x);
            const float s = __ldg(sp + gy * WIDTH + x);
            rc[i % 7] = pack2(c, c * c);
            rs[i % 7] = pack2(s, s * s);
            if (i >= 6) {
                const int o = i - 6;           // output row within tile
                u64 a = 0ull, d = 0ull;        // (c_mean, c_E2), (s_mean, s_E2)
                #pragma unroll
                for (int k = 0; k < 7; ++k) {
                    const int q = (o + k) % 7; // compile-time after unroll
                    a = fma2(G2[k], rc[q], a);
                    d = fma2(G2[k], rs[q], d);
                }
                ulonglong2 v; v.x = a; v.y = d;
                *reinterpret_cast<ulonglong2*>(sm + o * ROWB + vboff(x)) = v;
            }
        }
    }
    __syncthreads();

    // ---- Stage 2: horizontal 7-tap + AdaIN epilogue; 1 task per thread -----
    // 512 tasks = TH(8) rows x 64 chunks of 8 pixels.
    {
        const int row  = tid >> 6;             // 0..TH-1
        const int xc   = (tid & 63) << 3;      // chunk start column, 8-aligned
        const int gy   = y0 + row;
        const unsigned char* smrow = sm + row * ROWB;

        // hoist raw-content loads (overlap their latency with the FFMA2 stream)
        const float4 cA = *reinterpret_cast<const float4*>(cp + gy * WIDTH + xc);
        const float4 cB = *reinterpret_cast<const float4*>(cp + gy * WIDTH + xc + 4);

        u64 ac[8], as_[8];                     // packed accumulators per pixel
        #pragma unroll
        for (int o = 0; o < 8; ++o) { ac[o] = 0ull; as_[o] = 0ull; }

        #pragma unroll
        for (int j = 0; j < 14; ++j) {
            const int xi = refl(xc - 3 + j, WIDTH);
            const ulonglong2 w =
                *reinterpret_cast<const ulonglong2*>(smrow + vboff(xi));
            #pragma unroll
            for (int o = 0; o < 8; ++o) {
                const int k = j - o;
                if (k >= 0 && k < 7) {         // compile-time predicate
                    ac[o]  = fma2(G2[k], w.x, ac[o]);
                    as_[o] = fma2(G2[k], w.y, as_[o]);
                }
            }
        }

        const float craw[8] = {cA.x, cA.y, cA.z, cA.w, cB.x, cB.y, cB.z, cB.w};

        float res[8];
        #pragma unroll
        for (int o = 0; o < 8; ++o) {
            float cm, cE2, smn, sE2;
            unpack2(ac[o],  cm,  cE2);
            unpack2(as_[o], smn, sE2);
            const float cv = fmaxf(fmaf(-cm,  cm,  cE2), 1e-6f);
            const float sv = fmaxf(fmaf(-smn, smn, sE2), 1e-6f);
            const float rqc = frsq_ap(cv);              // MUFU.RSQ (parallel)
            const float rqs = frsq_ap(sv);              // MUFU.RSQ (parallel)
            const float numer = fmaf(sv, rqs, 1e-5f);   // sqrt(sv) + eps
            const float dinv  = rqc - (1e-5f * rqc) * rqc; // ~1/(sqrt(cv)+eps)
            res[o] = fmaf(craw[o] - cm, numer * dinv, smn);
        }

        *reinterpret_cast<float4*>(op + gy * WIDTH + xc) =
            make_float4(res[0], res[1], res[2], res[3]);
        *reinterpret_cast<float4*>(op + gy * WIDTH + xc + 4) =
            make_float4(res[4], res[5], res[6], res[7]);
    }
}

extern "C" void kernel_launch(void* const* d_in, const int* in_sizes, int n_in,
                              void* d_out, int out_size) {
    const float* content = (const float*)d_in[0];
    const float* style   = (const float*)d_in[1];
    float*       out     = (float*)d_out;

    const int planes = in_sizes[0] / (WIDTH * HEIGHT);   // 4*64 = 256

    cudaFuncSetAttribute(adain_local_kernel,
                         cudaFuncAttributeMaxDynamicSharedMemorySize, SMEM_BYTES);

    dim3 grid(HEIGHT / TH, planes);
    adain_local_kernel<<<grid, NTH, SMEM_BYTES>>>(content, style, out);
}

// round 9
// speedup vs baseline: 1.1955x; 1.1955x over previous
#include <cuda_runtime.h>

#define WIDTH   512
#define HEIGHT  512
#define TH      8                  // output rows per CTA
#define NTH     256                // threads per CTA
#define ROWB    (WIDTH * 16)       // bytes per SMEM vb row (512 x 16B tuples)
#define SMEM_BYTES (TH * ROWB)     // 65536

typedef unsigned long long u64;

// reflect padding (pad=3 < dim, single reflection suffices)
__device__ __forceinline__ int refl(int i, int n) {
    i = i < 0 ? -i : i;
    return i >= n ? 2 * n - 2 - i : i;
}

// XOR swizzle: byte offset of tuple #x within a vb row.
__device__ __forceinline__ unsigned vboff(int x) {
    return (unsigned)((x ^ ((x >> 3) & 7)) << 4);
}

__device__ __forceinline__ u64 pack2(float lo, float hi) {
    u64 r; asm("mov.b64 %0, {%1, %2};" : "=l"(r) : "f"(lo), "f"(hi)); return r;
}
__device__ __forceinline__ void unpack2(u64 v, float& lo, float& hi) {
    asm("mov.b64 {%0, %1}, %2;" : "=f"(lo), "=f"(hi) : "l"(v));
}
// packed dual FMA -> FFMA2 in SASS (PTX-only form)
__device__ __forceinline__ u64 fma2(u64 a, u64 b, u64 c) {
    u64 d; asm("fma.rn.f32x2 %0, %1, %2, %3;" : "=l"(d) : "l"(a), "l"(b), "l"(c));
    return d;
}
__device__ __forceinline__ float frsq_ap(float x) {
    float r; asm("rsqrt.approx.f32 %0, %1;" : "=f"(r) : "f"(x)); return r;
}

// Stage-1 vertical blur for one column. EDGE=false: zero per-row address ALU
// (immediate-offset LDGs off two base pointers). EDGE=true: R6's refl path.
template<bool EDGE>
__device__ __forceinline__ void stage1_col(const float* __restrict__ cp,
                                           const float* __restrict__ sp,
                                           unsigned char* sm,
                                           int x, int y0, const u64* G2) {
    const unsigned sb = vboff(x);
    u64 rc[7], rs[7];                          // ring: packed (v, v^2)
    const float* cr = cp + (y0 - 3) * WIDTH + x;   // valid base when !EDGE
    const float* sr = sp + (y0 - 3) * WIDTH + x;
    #pragma unroll
    for (int i = 0; i < TH + 6; ++i) {
        float c, s;
        if (EDGE) {
            const int gy = refl(y0 - 3 + i, HEIGHT);
            c = __ldg(cp + gy * WIDTH + x);
            s = __ldg(sp + gy * WIDTH + x);
        } else {
            c = __ldg(cr + i * WIDTH);         // LDG [R + imm]
            s = __ldg(sr + i * WIDTH);
        }
        rc[i % 7] = pack2(c, c * c);
        rs[i % 7] = pack2(s, s * s);
        if (i >= 6) {
            const int o = i - 6;               // output row within tile
            u64 a = 0ull, d = 0ull;            // (mean, E2) packed per tensor
            #pragma unroll
            for (int k = 0; k < 7; ++k) {
                const int q = (o + k) % 7;     // compile-time after unroll
                a = fma2(G2[k], rc[q], a);
                d = fma2(G2[k], rs[q], d);
            }
            ulonglong2 v; v.x = a; v.y = d;
            *reinterpret_cast<ulonglong2*>(sm + o * ROWB + sb) = v;
        }
    }
}

__global__ __launch_bounds__(NTH, 3)
void adain_local_kernel(const float* __restrict__ content,
                        const float* __restrict__ style,
                        float* __restrict__ out) {
    extern __shared__ unsigned char sm[];

    const float G[7] = {0.0044330481752437f, 0.0540055826224143f,
                        0.2420362293761143f, 0.3990502746173879f,
                        0.2420362293761143f, 0.0540055826224143f,
                        0.0044330481752437f};
    u64 G2[7];
    #pragma unroll
    for (int k = 0; k < 7; ++k) G2[k] = pack2(G[k], G[k]);

    const int plane = blockIdx.y;
    const int y0    = blockIdx.x * TH;
    const size_t pb = (size_t)plane * (WIDTH * HEIGHT);
    const float* cp = content + pb;
    const float* sp = style   + pb;
    float*       op = out     + pb;
    const int tid = threadIdx.x;

    // -------- Stage 1: vertical 7-tap blur; each thread handles 2 columns ---
    // 62/64 y-tiles take the zero-ALU interior path.
    if (y0 >= 3 && y0 + TH + 3 <= HEIGHT) {
        stage1_col<false>(cp, sp, sm, tid,       y0, G2);
        stage1_col<false>(cp, sp, sm, tid + NTH, y0, G2);
    } else {
        stage1_col<true >(cp, sp, sm, tid,       y0, G2);
        stage1_col<true >(cp, sp, sm, tid + NTH, y0, G2);
    }
    __syncthreads();

    // ---- Stage 2: horizontal 7-tap + AdaIN epilogue (R6-proven, unchanged) --
    #pragma unroll
    for (int t = 0; t < 2; ++t) {
        const int task = tid + t * NTH;
        const int row  = task >> 6;            // 0..TH-1
        const int xc   = (task & 63) << 3;     // chunk start column, 8-aligned
        const int gy   = y0 + row;
        const unsigned char* smrow = sm + row * ROWB;

        // hoist raw-content loads (overlap their latency with the FFMA2 stream)
        const float4 cA = *reinterpret_cast<const float4*>(cp + gy * WIDTH + xc);
        const float4 cB = *reinterpret_cast<const float4*>(cp + gy * WIDTH + xc + 4);

        u64 ac[8], as_[8];                     // packed accumulators per pixel
        #pragma unroll
        for (int o = 0; o < 8; ++o) { ac[o] = 0ull; as_[o] = 0ull; }

        #pragma unroll
        for (int j = 0; j < 14; ++j) {
            const int xi = refl(xc - 3 + j, WIDTH);
            const ulonglong2 w =
                *reinterpret_cast<const ulonglong2*>(smrow + vboff(xi));
            #pragma unroll
            for (int o = 0; o < 8; ++o) {
                const int k = j - o;
                if (k >= 0 && k < 7) {         // compile-time predicate
                    ac[o]  = fma2(G2[k], w.x, ac[o]);
                    as_[o] = fma2(G2[k], w.y, as_[o]);
                }
            }
        }

        const float craw[8] = {cA.x, cA.y, cA.z, cA.w, cB.x, cB.y, cB.z, cB.w};

        float res[8];
        #pragma unroll
        for (int o = 0; o < 8; ++o) {
            float cm, cE2, smn, sE2;
            unpack2(ac[o],  cm,  cE2);
            unpack2(as_[o], smn, sE2);
            const float cv = fmaxf(fmaf(-cm,  cm,  cE2), 1e-6f);
            const float sv = fmaxf(fmaf(-smn, smn, sE2), 1e-6f);
            const float rqc = frsq_ap(cv);              // MUFU.RSQ (parallel)
            const float rqs = frsq_ap(sv);              // MUFU.RSQ (parallel)
            const float numer = fmaf(sv, rqs, 1e-5f);   // sqrt(sv) + eps
            const float dinv  = rqc - (1e-5f * rqc) * rqc; // ~1/(sqrt(cv)+eps)
            res[o] = fmaf(craw[o] - cm, numer * dinv, smn);
        }

        *reinterpret_cast<float4*>(op + gy * WIDTH + xc) =
            make_float4(res[0], res[1], res[2], res[3]);
        *reinterpret_cast<float4*>(op + gy * WIDTH + xc + 4) =
            make_float4(res[4], res[5], res[6], res[7]);
    }
}

extern "C" void kernel_launch(void* const* d_in, const int* in_sizes, int n_in,
                              void* d_out, int out_size) {
    const float* content = (const float*)d_in[0];
    const float* style   = (const float*)d_in[1];
    float*       out     = (float*)d_out;

    const int planes = in_sizes[0] / (WIDTH * HEIGHT);   // 4*64 = 256

    cudaFuncSetAttribute(adain_local_kernel,
                         cudaFuncAttributeMaxDynamicSharedMemorySize, SMEM_BYTES);

    dim3 grid(HEIGHT / TH, planes);
    adain_local_kernel<<<grid, NTH, SMEM_BYTES>>>(content, style, out);
}